// round 1
// baseline (speedup 1.0000x reference)
#include <cuda_runtime.h>

// Problem constants (fixed by the dataset)
#define NGROUPS 512   // B*S/16 = 4*2048/16
#define NSLOTS  64    // E*Sets = 16*4
#define DDIM    512
#define TTOK    16
#define FDIM    32

// winner token index per (group, slot)
__device__ int g_winners[NGROUPS * NSLOTS];

// ---------------------------------------------------------------------------
// Kernel 1: routing. One CTA per group of 16 tokens.
//  - loads the 16x512 token tile to smem (contiguous 32KB)
//  - zeroes this group's output tile (out is poisoned by the harness)
//  - computes 16x64 controller logits, adds the linspace tie-breaker
//  - argmax over tokens per slot; fp64 recheck when the top-2 gap is tiny
// ---------------------------------------------------------------------------
__global__ __launch_bounds__(256) void k_route(const float* __restrict__ x,
                                               const float* __restrict__ ctrl,
                                               float* __restrict__ out)
{
    __shared__ float xs[TTOK * DDIM];     // 32 KB
    __shared__ float ls[NSLOTS * TTOK];   // 4 KB logits staging
    const int G = blockIdx.x;

    // Token tile of a group is one contiguous 8192-float block.
    const float4* src = (const float4*)(x + (size_t)G * TTOK * DDIM);
    float4* xs4 = (float4*)xs;
    for (int i = threadIdx.x; i < TTOK * DDIM / 4; i += 256) xs4[i] = src[i];

    // Zero-init this group's output tile (atomics accumulate into it later).
    float4* dst = (float4*)(out + (size_t)G * TTOK * DDIM);
    const float4 z4 = make_float4(0.f, 0.f, 0.f, 0.f);
    for (int i = threadIdx.x; i < TTOK * DDIM / 4; i += 256) dst[i] = z4;
    __syncthreads();

    // 256 threads = 64 slots x 4 token-quads. Each thread: 4 tokens, 1 slot.
    const int slot = threadIdx.x & 63;
    const int tq   = threadIdx.x >> 6;    // 0..3
    const int t0   = tq * 4;
    const float* xr0 = xs + (t0 + 0) * DDIM;
    const float* xr1 = xr0 + DDIM;
    const float* xr2 = xr1 + DDIM;
    const float* xr3 = xr2 + DDIM;
    const float* cp  = ctrl + slot;       // ctrl[d*64 + slot]

    float a0 = 0.f, a1 = 0.f, a2 = 0.f, a3 = 0.f;
    #pragma unroll 8
    for (int k = 0; k < DDIM; ++k) {
        float c = __ldg(cp + k * 64);     // coalesced across lanes (slot-contig)
        a0 = fmaf(xr0[k], c, a0);
        a1 = fmaf(xr1[k], c, a1);
        a2 = fmaf(xr2[k], c, a2);
        a3 = fmaf(xr3[k], c, a3);
    }
    const float step = 1e-6f / 15.f;      // jnp.linspace(0, 1e-6, 16) spacing
    ls[slot * TTOK + t0 + 0] = a0 + step * (float)(t0 + 0);
    ls[slot * TTOK + t0 + 1] = a1 + step * (float)(t0 + 1);
    ls[slot * TTOK + t0 + 2] = a2 + step * (float)(t0 + 2);
    ls[slot * TTOK + t0 + 3] = a3 + step * (float)(t0 + 3);
    __syncthreads();

    if (threadIdx.x < 64) {
        const int s = threadIdx.x;
        float best = -3.4e38f, second = -3.4e38f;
        int bi = 0;
        #pragma unroll
        for (int t = 0; t < TTOK; ++t) {
            float v = ls[s * TTOK + t];
            if (v >= best) { second = best; best = v; bi = t; }
            else if (v > second) { second = v; }
        }
        // Near-tie safety net: fp32 rounding (~1e-6) can flip the argmax when
        // the gap is tiny. Recompute this slot's logits in fp64 (rare path).
        if (best - second < 3e-4f) {
            double dbest = -1e300; int dbi = 0;
            for (int t = 0; t < TTOK; ++t) {
                double acc = 0.0;
                const float* xr = xs + t * DDIM;
                for (int k = 0; k < DDIM; ++k)
                    acc += (double)xr[k] * (double)__ldg(ctrl + k * 64 + s);
                acc += (double)t * (1e-6 / 15.0);
                if (acc >= dbest) { dbest = acc; dbi = t; }
            }
            bi = dbi;
        }
        g_winners[G * 64 + s] = bi;
    }
}

// ---------------------------------------------------------------------------
// Kernel 2: per-slot expert FFN. Grid (16 group-chunks, 64 slots).
// Each CTA: 32 groups for one slot.
//   gather 32 winner rows -> Xg[32][512] (smem)
//   GEMM1: Y[32][32] = Xg @ f1[:,slot,:]   (relu)   -> YT smem, f-major padded
//   GEMM2: Z[32][512] = Y @ f2[slot]                -> registers
//   scatter: atomicAdd float2 into winner output rows
// ---------------------------------------------------------------------------
__global__ __launch_bounds__(256) void k_expert(const float* __restrict__ x,
                                                const float* __restrict__ f1,
                                                const float* __restrict__ f2,
                                                float* __restrict__ out)
{
    extern __shared__ float sm[];
    float* Xg = sm;                        // 32*512 floats = 64 KB
    float* YT = sm + 32 * DDIM;            // [32 f][36 pad] = 4.5 KB
    __shared__ int rowb[32];

    const int slot = blockIdx.y;
    const int g0   = blockIdx.x * 32;
    const int tid  = threadIdx.x;

    if (tid < 32) {
        int w = g_winners[(g0 + tid) * 64 + slot];
        rowb[tid] = ((g0 + tid) * TTOK + w) * DDIM;
    }
    __syncthreads();

    // Gather winner rows (coalesced float4 per row).
    for (int i = tid; i < 32 * (DDIM / 4); i += 256) {
        int r  = i >> 7;        // DDIM/4 = 128
        int k4 = i & 127;
        ((float4*)(Xg + r * DDIM))[k4] = __ldg((const float4*)(x + rowb[r]) + k4);
    }
    __syncthreads();

    // ---- GEMM1: thread = (f = lane, 4 rows). W1 read coalesced from L1/L2.
    {
        const int f  = tid & 31;
        const int rq = tid >> 5;
        const float* w1p = f1 + slot * 32 + f;      // f1[d*2048 + slot*32 + f]
        const float* xr0 = Xg + (rq * 4 + 0) * DDIM;
        const float* xr1 = xr0 + DDIM;
        const float* xr2 = xr1 + DDIM;
        const float* xr3 = xr2 + DDIM;
        float a0 = 0.f, a1 = 0.f, a2 = 0.f, a3 = 0.f;
        #pragma unroll 8
        for (int k = 0; k < DDIM; ++k) {
            float w = __ldg(w1p + k * 2048);
            a0 = fmaf(xr0[k], w, a0);
            a1 = fmaf(xr1[k], w, a1);
            a2 = fmaf(xr2[k], w, a2);
            a3 = fmaf(xr3[k], w, a3);
        }
        // relu + store f-major (GEMM2 contracts over f): YT[f][r], pad 36
        YT[f * 36 + rq * 4 + 0] = fmaxf(a0, 0.f);
        YT[f * 36 + rq * 4 + 1] = fmaxf(a1, 0.f);
        YT[f * 36 + rq * 4 + 2] = fmaxf(a2, 0.f);
        YT[f * 36 + rq * 4 + 3] = fmaxf(a3, 0.f);
    }
    __syncthreads();

    // ---- GEMM2: warp owns a 64-wide d-chunk; lane owns 2 d. acc[32 rows][2].
    {
        const int lane = tid & 31;
        const int wq   = tid >> 5;
        const int d0   = wq * 64 + lane * 2;
        float acc[32][2];
        #pragma unroll
        for (int r = 0; r < 32; ++r) { acc[r][0] = 0.f; acc[r][1] = 0.f; }

        const float* w2p = f2 + slot * (FDIM * DDIM) + d0;  // f2[slot*16384 + k*512 + d]
        #pragma unroll 4
        for (int k = 0; k < FDIM; ++k) {
            float2 wv = __ldg((const float2*)(w2p + k * DDIM));
            const float* yk = YT + k * 36;
            #pragma unroll
            for (int r4 = 0; r4 < 8; ++r4) {
                float4 y = *(const float4*)(yk + r4 * 4);   // broadcast LDS.128
                acc[r4*4+0][0] = fmaf(y.x, wv.x, acc[r4*4+0][0]);
                acc[r4*4+0][1] = fmaf(y.x, wv.y, acc[r4*4+0][1]);
                acc[r4*4+1][0] = fmaf(y.y, wv.x, acc[r4*4+1][0]);
                acc[r4*4+1][1] = fmaf(y.y, wv.y, acc[r4*4+1][1]);
                acc[r4*4+2][0] = fmaf(y.z, wv.x, acc[r4*4+2][0]);
                acc[r4*4+2][1] = fmaf(y.z, wv.y, acc[r4*4+2][1]);
                acc[r4*4+3][0] = fmaf(y.w, wv.x, acc[r4*4+3][0]);
                acc[r4*4+3][1] = fmaf(y.w, wv.y, acc[r4*4+3][1]);
            }
        }
        // Scatter-add into winner rows (8B-aligned float2 atomics, coalesced).
        #pragma unroll
        for (int r = 0; r < 32; ++r) {
            float2* p = (float2*)(out + rowb[r] + d0);
            atomicAdd(p, make_float2(acc[r][0], acc[r][1]));
        }
    }
}

// ---------------------------------------------------------------------------
extern "C" void kernel_launch(void* const* d_in, const int* in_sizes, int n_in,
                              void* d_out, int out_size)
{
    (void)in_sizes; (void)n_in; (void)out_size;
    const float* x    = (const float*)d_in[0];  // [4,2048,512]
    const float* ctrl = (const float*)d_in[1];  // [512,16,4]
    const float* f1   = (const float*)d_in[2];  // [512,16,4,32]
    const float* f2   = (const float*)d_in[3];  // [16,4,32,512]
    float* out = (float*)d_out;

    const int smem2 = (32 * DDIM + 32 * 36) * (int)sizeof(float);  // 70144 B
    cudaFuncSetAttribute(k_expert, cudaFuncAttributeMaxDynamicSharedMemorySize, smem2);

    k_route<<<NGROUPS, 256>>>(x, ctrl, out);
    k_expert<<<dim3(16, 64), 256, smem2>>>(x, f1, f2, out);
}

// round 2
// speedup vs baseline: 1.1691x; 1.1691x over previous
#include <cuda_runtime.h>

#define NGROUPS 512   // B*S/16
#define NSLOTS  64    // E*Sets
#define DDIM    512
#define TTOK    16
#define FDIM    32

typedef unsigned long long ull;
union U2 { ull u; float2 f; };

// packed fp32x2 FMA (sm_100+): d.lo += a.lo*b.lo ; d.hi += a.hi*b.hi
__device__ __forceinline__ void ffma2(ull& d, ull a, ull b) {
    asm("fma.rn.f32x2 %0, %1, %2, %0;" : "+l"(d) : "l"(a), "l"(b));
}
__device__ __forceinline__ ull bcast2(float x) {
    ull r; asm("mov.b64 %0, {%1, %1};" : "=l"(r) : "f"(x)); return r;
}

__device__ int g_winners[NGROUPS * NSLOTS];

// ---------------------------------------------------------------------------
// Kernel 1: routing. One CTA per group. 256 thr = 16 slot-quads x 4 token-
// quads x 4 k-chunks. Per 4k: 4 LDS.128(x, broadcast) + 4 LDG.128(ctrl,
// coalesced) + 32 FFMA2. Partials reduced through smem; argmax with fp64
// near-tie recheck (exactness of the permutation is load-bearing).
// ---------------------------------------------------------------------------
__global__ __launch_bounds__(256) void k_route(const float* __restrict__ x,
                                               const float* __restrict__ ctrl,
                                               float* __restrict__ out)
{
    extern __shared__ float sm[];
    float* xs   = sm;                 // 16 x 512 tokens, row-major (32 KB)
    float* part = sm + 8192;          // 256 x 16 partials (16 KB)
    float* ls   = sm + 8192 + 4096;   // 64 x 16 logits (4 KB)
    const int G   = blockIdx.x;
    const int tid = threadIdx.x;

    // load token tile + zero-init this group's output tile
    const float4* src = (const float4*)(x + (size_t)G * 8192);
    float4* dst = (float4*)(out + (size_t)G * 8192);
    float4* xs4 = (float4*)xs;
    const float4 z4 = make_float4(0.f, 0.f, 0.f, 0.f);
    for (int i = tid; i < 2048; i += 256) { xs4[i] = src[i]; dst[i] = z4; }
    __syncthreads();

    {
        const int sq = tid & 15;          // slot quad (4 slots)
        const int tq = (tid >> 4) & 3;    // token quad (4 tokens)
        const int ks = tid >> 6;          // k chunk of 128
        const int kbase = ks * 128;

        U2 acc[4][2];
        #pragma unroll
        for (int t = 0; t < 4; ++t) { acc[t][0].u = 0ull; acc[t][1].u = 0ull; }

        const float* cbase = ctrl + sq * 4;
        const float* x0 = xs + tq * 4 * DDIM;

        for (int kk = 0; kk < 128; kk += 4) {
            const int k = kbase + kk;
            float xv[4][4];
            #pragma unroll
            for (int t = 0; t < 4; ++t)
                *(float4*)&xv[t][0] = *(const float4*)(x0 + t * DDIM + k);
            #pragma unroll
            for (int j = 0; j < 4; ++j) {
                const ulonglong2 w = __ldg((const ulonglong2*)(cbase + (size_t)(k + j) * 64));
                #pragma unroll
                for (int t = 0; t < 4; ++t) {
                    ull xb = bcast2(xv[t][j]);
                    ffma2(acc[t][0].u, xb, w.x);
                    ffma2(acc[t][1].u, xb, w.y);
                }
            }
        }
        #pragma unroll
        for (int t = 0; t < 4; ++t) {
            part[tid * 16 + t * 4 + 0] = acc[t][0].f.x;
            part[tid * 16 + t * 4 + 1] = acc[t][0].f.y;
            part[tid * 16 + t * 4 + 2] = acc[t][1].f.x;
            part[tid * 16 + t * 4 + 3] = acc[t][1].f.y;
        }
    }
    __syncthreads();

    // reduce k-chunks, add linspace tie-breaker -> ls[slot][token]
    {
        const int s   = tid & 63;
        const int tq2 = tid >> 6;
        const int sq2 = s >> 2, sl = s & 3;
        const float step = 1e-6f / 15.f;
        #pragma unroll
        for (int tl = 0; tl < 4; ++tl) {
            float v = 0.f;
            #pragma unroll
            for (int c = 0; c < 4; ++c)
                v += part[(c * 64 + tq2 * 16 + sq2) * 16 + tl * 4 + sl];
            const int t = tq2 * 4 + tl;
            ls[s * 16 + t] = v + step * (float)t;
        }
    }
    __syncthreads();

    if (tid < 64) {
        const int s = tid;
        float best = -3.4e38f, second = -3.4e38f;
        int bi = 0;
        #pragma unroll
        for (int t = 0; t < TTOK; ++t) {
            float v = ls[s * 16 + t];
            if (v >= best) { second = best; best = v; bi = t; }
            else if (v > second) { second = v; }
        }
        if (best - second < 3e-4f) {   // fp64 recheck on near ties (rare)
            double dbest = -1e300; int dbi = 0;
            for (int t = 0; t < TTOK; ++t) {
                double a = 0.0;
                const float* xr = xs + t * DDIM;
                for (int k = 0; k < DDIM; ++k)
                    a += (double)xr[k] * (double)__ldg(ctrl + k * 64 + s);
                a += (double)t * (1e-6 / 15.0);
                if (a >= dbest) { dbest = a; dbi = t; }
            }
            bi = dbi;
        }
        g_winners[G * 64 + s] = bi;
    }
}

// ---------------------------------------------------------------------------
// Kernel 2: per-slot expert FFN. Grid (16 group-chunks, 64 slots), 32 rows/CTA.
//  gather winners -> Xg (row-major, broadcast-friendly)
//  GEMM1 (k-split 4): per 4k: 4 LDS.128 + 4 LDG.128(f1) + 32 FFMA2
//  reduce+relu -> YT[f][r] (stride 36)
//  GEMM2: row-pair accumulators; YT pairs free via LDS.128, f2 d-pairs free
//  scatter-add with float2 atomics
// ---------------------------------------------------------------------------
__global__ __launch_bounds__(256, 2) void k_expert(const float* __restrict__ x,
                                                   const float* __restrict__ f1,
                                                   const float* __restrict__ f2,
                                                   float* __restrict__ out)
{
    extern __shared__ float sm[];
    float* Xg   = sm;                    // 32 x 512 (64 KB)
    float* part = sm + 16384;            // 256 x 16 (16 KB)
    float* YT   = sm + 16384 + 4096;     // 32 f x 36 (4.5 KB)
    __shared__ int rowb[32];

    const int slot = blockIdx.y;
    const int g0   = blockIdx.x * 32;
    const int tid  = threadIdx.x;

    if (tid < 32) {
        int w = g_winners[(g0 + tid) * 64 + slot];
        rowb[tid] = ((g0 + tid) * TTOK + w) * DDIM;
    }
    __syncthreads();

    for (int i = tid; i < 32 * 128; i += 256) {
        int r = i >> 7, k4 = i & 127;
        *(float4*)(Xg + r * DDIM + k4 * 4) = __ldg((const float4*)(x + rowb[r]) + k4);
    }
    __syncthreads();

    // ---- GEMM1
    {
        const int fq = tid & 7;
        const int rq = (tid >> 3) & 7;
        const int ks = tid >> 6;
        const int kbase = ks * 128;

        U2 acc[4][2];
        #pragma unroll
        for (int r = 0; r < 4; ++r) { acc[r][0].u = 0ull; acc[r][1].u = 0ull; }

        const float* wb = f1 + slot * 32 + fq * 4;
        const float* xr = Xg + rq * 4 * DDIM;

        for (int kk = 0; kk < 128; kk += 4) {
            const int k = kbase + kk;
            float xv[4][4];
            #pragma unroll
            for (int r = 0; r < 4; ++r)
                *(float4*)&xv[r][0] = *(const float4*)(xr + r * DDIM + k);
            #pragma unroll
            for (int j = 0; j < 4; ++j) {
                const ulonglong2 w = __ldg((const ulonglong2*)(wb + (size_t)(k + j) * 2048));
                #pragma unroll
                for (int r = 0; r < 4; ++r) {
                    ull xb = bcast2(xv[r][j]);
                    ffma2(acc[r][0].u, xb, w.x);
                    ffma2(acc[r][1].u, xb, w.y);
                }
            }
        }
        #pragma unroll
        for (int r = 0; r < 4; ++r) {
            part[tid * 16 + r * 4 + 0] = acc[r][0].f.x;
            part[tid * 16 + r * 4 + 1] = acc[r][0].f.y;
            part[tid * 16 + r * 4 + 2] = acc[r][1].f.x;
            part[tid * 16 + r * 4 + 3] = acc[r][1].f.y;
        }
    }
    __syncthreads();

    // reduce + relu -> YT[f*36 + r]
    {
        const int r  = tid >> 3;
        const int fq = tid & 7;
        #pragma unroll
        for (int fl = 0; fl < 4; ++fl) {
            float v = 0.f;
            #pragma unroll
            for (int c = 0; c < 4; ++c)
                v += part[(c * 64 + (r >> 2) * 8 + fq) * 16 + (r & 3) * 4 + fl];
            YT[(fq * 4 + fl) * 36 + r] = fmaxf(v, 0.f);
        }
    }
    __syncthreads();

    // ---- GEMM2: warp owns 64-wide d chunk, lane owns 2 d; acc over row-pairs
    {
        const int lane = tid & 31;
        const int wq   = tid >> 5;
        const int d0   = wq * 64 + lane * 2;

        U2 acc[16][2];
        #pragma unroll
        for (int p = 0; p < 16; ++p) { acc[p][0].u = 0ull; acc[p][1].u = 0ull; }

        const float* w2p = f2 + slot * (FDIM * DDIM) + d0;
        #pragma unroll 4
        for (int k = 0; k < FDIM; ++k) {
            const float2 wv = __ldg((const float2*)(w2p + k * DDIM));
            const ull wb0 = bcast2(wv.x);
            const ull wb1 = bcast2(wv.y);
            const ulonglong2* yp = (const ulonglong2*)(YT + k * 36);
            #pragma unroll
            for (int q = 0; q < 8; ++q) {
                const ulonglong2 y = yp[q];     // rows (4q,4q+1),(4q+2,4q+3)
                ffma2(acc[2*q  ][0].u, y.x, wb0);
                ffma2(acc[2*q  ][1].u, y.x, wb1);
                ffma2(acc[2*q+1][0].u, y.y, wb0);
                ffma2(acc[2*q+1][1].u, y.y, wb1);
            }
        }
        #pragma unroll
        for (int p = 0; p < 16; ++p) {
            atomicAdd((float2*)(out + rowb[2*p    ] + d0),
                      make_float2(acc[p][0].f.x, acc[p][1].f.x));
            atomicAdd((float2*)(out + rowb[2*p + 1] + d0),
                      make_float2(acc[p][0].f.y, acc[p][1].f.y));
        }
    }
}

// ---------------------------------------------------------------------------
extern "C" void kernel_launch(void* const* d_in, const int* in_sizes, int n_in,
                              void* d_out, int out_size)
{
    (void)in_sizes; (void)n_in; (void)out_size;
    const float* x    = (const float*)d_in[0];
    const float* ctrl = (const float*)d_in[1];
    const float* f1   = (const float*)d_in[2];
    const float* f2   = (const float*)d_in[3];
    float* out = (float*)d_out;

    const int smem1 = (8192 + 4096 + 1024) * (int)sizeof(float);   // 53248
    const int smem2 = (16384 + 4096 + 1152) * (int)sizeof(float);  // 86528
    cudaFuncSetAttribute(k_route,  cudaFuncAttributeMaxDynamicSharedMemorySize, smem1);
    cudaFuncSetAttribute(k_expert, cudaFuncAttributeMaxDynamicSharedMemorySize, smem2);

    k_route<<<NGROUPS, 256, smem1>>>(x, ctrl, out);
    k_expert<<<dim3(16, 64), 256, smem2>>>(x, f1, f2, out);
}

// round 3
// speedup vs baseline: 3.1365x; 2.6829x over previous
#include <cuda_runtime.h>

#define NGROUPS 512   // B*S/16
#define NSLOTS  64    // E*Sets
#define DDIM    512
#define TTOK    16
#define FDIM    32

typedef unsigned long long ull;
union U2 { ull u; float2 f; };

// packed fp32x2 FMA (sm_100+): d.lo += a.lo*b.lo ; d.hi += a.hi*b.hi
__device__ __forceinline__ void ffma2(ull& d, ull a, ull b) {
    asm("fma.rn.f32x2 %0, %1, %2, %0;" : "+l"(d) : "l"(a), "l"(b));
}
__device__ __forceinline__ ull bcast2(float x) {
    ull r; asm("mov.b64 %0, {%1, %1};" : "=l"(r) : "f"(x)); return r;
}

__device__ int g_winners[NGROUPS * NSLOTS];

// ---------------------------------------------------------------------------
// Kernel 1: routing. One CTA per group. FFMA2 main path; near-ties (gap<2e-5)
// resolved by a CTA-COOPERATIVE fp64 recheck (256 threads: 16 tokens x 16
// k-chunks, deterministic reduction) instead of a single-thread serial chain.
// ---------------------------------------------------------------------------
__global__ __launch_bounds__(256) void k_route(const float* __restrict__ x,
                                               const float* __restrict__ ctrl,
                                               float* __restrict__ out)
{
    extern __shared__ float sm[];
    float* xs   = sm;                        // 16 x 512 tokens (32 KB)
    float* part = sm + 8192;                 // 256 x 16 partials (16 KB)
    float* ls   = sm + 12288;                // 64 x 16 logits (4 KB)
    double* dred = (double*)(sm + 13312);    // 256 doubles (2 KB)
    __shared__ int sflags[64];
    __shared__ int swin[64];
    __shared__ int snf;
    __shared__ double dlog[16];

    const int G   = blockIdx.x;
    const int tid = threadIdx.x;

    if (tid == 0) snf = 0;

    // load token tile + zero-init this group's output tile
    const float4* src = (const float4*)(x + (size_t)G * 8192);
    float4* dst = (float4*)(out + (size_t)G * 8192);
    float4* xs4 = (float4*)xs;
    const float4 z4 = make_float4(0.f, 0.f, 0.f, 0.f);
    for (int i = tid; i < 2048; i += 256) { xs4[i] = src[i]; dst[i] = z4; }
    __syncthreads();

    {
        const int sq = tid & 15;          // slot quad (4 slots)
        const int tq = (tid >> 4) & 3;    // token quad (4 tokens)
        const int ks = tid >> 6;          // k chunk of 128
        const int kbase = ks * 128;

        U2 acc[4][2];
        #pragma unroll
        for (int t = 0; t < 4; ++t) { acc[t][0].u = 0ull; acc[t][1].u = 0ull; }

        const float* cbase = ctrl + sq * 4;
        const float* x0 = xs + tq * 4 * DDIM;

        for (int kk = 0; kk < 128; kk += 4) {
            const int k = kbase + kk;
            ulonglong2 w[4];
            #pragma unroll
            for (int j = 0; j < 4; ++j)
                w[j] = __ldg((const ulonglong2*)(cbase + (size_t)(k + j) * 64));
            float xv[4][4];
            #pragma unroll
            for (int t = 0; t < 4; ++t)
                *(float4*)&xv[t][0] = *(const float4*)(x0 + t * DDIM + k);
            #pragma unroll
            for (int j = 0; j < 4; ++j) {
                #pragma unroll
                for (int t = 0; t < 4; ++t) {
                    ull xb = bcast2(xv[t][j]);
                    ffma2(acc[t][0].u, xb, w[j].x);
                    ffma2(acc[t][1].u, xb, w[j].y);
                }
            }
        }
        #pragma unroll
        for (int t = 0; t < 4; ++t) {
            part[tid * 16 + t * 4 + 0] = acc[t][0].f.x;
            part[tid * 16 + t * 4 + 1] = acc[t][0].f.y;
            part[tid * 16 + t * 4 + 2] = acc[t][1].f.x;
            part[tid * 16 + t * 4 + 3] = acc[t][1].f.y;
        }
    }
    __syncthreads();

    // reduce k-chunks, add linspace tie-breaker -> ls[slot][token]
    {
        const int s   = tid & 63;
        const int tq2 = tid >> 6;
        const int sq2 = s >> 2, sl = s & 3;
        const float step = 1e-6f / 15.f;
        #pragma unroll
        for (int tl = 0; tl < 4; ++tl) {
            float v = 0.f;
            #pragma unroll
            for (int c = 0; c < 4; ++c)
                v += part[(c * 64 + tq2 * 16 + sq2) * 16 + tl * 4 + sl];
            const int t = tq2 * 4 + tl;
            ls[s * 16 + t] = v + step * (float)t;
        }
    }
    __syncthreads();

    // fp32 argmax per slot; flag near-ties for cooperative fp64 recheck
    if (tid < 64) {
        const int s = tid;
        float best = -3.4e38f, second = -3.4e38f;
        int bi = 0;
        #pragma unroll
        for (int t = 0; t < TTOK; ++t) {
            float v = ls[s * 16 + t];
            if (v >= best) { second = best; best = v; bi = t; }
            else if (v > second) { second = v; }
        }
        swin[s] = bi;
        if (best - second < 2e-5f) {
            int p = atomicAdd(&snf, 1);
            sflags[p] = s;
        }
    }
    __syncthreads();

    // cooperative fp64 recheck of flagged slots (rare; ~2us each)
    const int nf = snf;
    for (int i = 0; i < nf; ++i) {
        const int s = sflags[i];
        const int t = tid >> 4, j = tid & 15;
        double a = 0.0;
        const float* xr = xs + t * DDIM + j * 32;
        const float* cp = ctrl + (size_t)(j * 32) * 64 + s;
        #pragma unroll 8
        for (int k = 0; k < 32; ++k)
            a += (double)xr[k] * (double)__ldg(cp + (size_t)k * 64);
        dred[t * 16 + j] = a;
        __syncthreads();
        if (tid < 16) {
            double tot = 0.0;
            #pragma unroll
            for (int j2 = 0; j2 < 16; ++j2) tot += dred[tid * 16 + j2];
            dlog[tid] = tot + (double)tid * (1e-6 / 15.0);
        }
        __syncthreads();
        if (tid == 0) {
            double best = -1e300; int bi = 0;
            #pragma unroll
            for (int t2 = 0; t2 < TTOK; ++t2)
                if (dlog[t2] >= best) { best = dlog[t2]; bi = t2; }
            swin[s] = bi;
        }
        __syncthreads();
    }

    if (tid < 64) g_winners[G * 64 + tid] = swin[tid];
}

// ---------------------------------------------------------------------------
// Kernel 2: per-slot expert FFN. Grid (16 group-chunks, 64 slots), 32 rows/CTA.
// ---------------------------------------------------------------------------
__global__ __launch_bounds__(256, 2) void k_expert(const float* __restrict__ x,
                                                   const float* __restrict__ f1,
                                                   const float* __restrict__ f2,
                                                   float* __restrict__ out)
{
    extern __shared__ float sm[];
    float* Xg   = sm;                    // 32 x 512 (64 KB)
    float* part = sm + 16384;            // 256 x 16 (16 KB)
    float* YT   = sm + 16384 + 4096;     // 32 f x 36 (4.5 KB)
    __shared__ int rowb[32];

    const int slot = blockIdx.y;
    const int g0   = blockIdx.x * 32;
    const int tid  = threadIdx.x;

    if (tid < 32) {
        int w = g_winners[(g0 + tid) * 64 + slot];
        rowb[tid] = ((g0 + tid) * TTOK + w) * DDIM;
    }
    __syncthreads();

    for (int i = tid; i < 32 * 128; i += 256) {
        int r = i >> 7, k4 = i & 127;
        *(float4*)(Xg + r * DDIM + k4 * 4) = __ldg((const float4*)(x + rowb[r]) + k4);
    }
    __syncthreads();

    // ---- GEMM1 (k-split 4): w loads hoisted ahead of FMA block (MLP=4)
    {
        const int fq = tid & 7;
        const int rq = (tid >> 3) & 7;
        const int ks = tid >> 6;
        const int kbase = ks * 128;

        U2 acc[4][2];
        #pragma unroll
        for (int r = 0; r < 4; ++r) { acc[r][0].u = 0ull; acc[r][1].u = 0ull; }

        const float* wb = f1 + slot * 32 + fq * 4;
        const float* xr = Xg + rq * 4 * DDIM;

        for (int kk = 0; kk < 128; kk += 4) {
            const int k = kbase + kk;
            ulonglong2 w[4];
            #pragma unroll
            for (int j = 0; j < 4; ++j)
                w[j] = __ldg((const ulonglong2*)(wb + (size_t)(k + j) * 2048));
            float xv[4][4];
            #pragma unroll
            for (int r = 0; r < 4; ++r)
                *(float4*)&xv[r][0] = *(const float4*)(xr + r * DDIM + k);
            #pragma unroll
            for (int j = 0; j < 4; ++j) {
                #pragma unroll
                for (int r = 0; r < 4; ++r) {
                    ull xb = bcast2(xv[r][j]);
                    ffma2(acc[r][0].u, xb, w[j].x);
                    ffma2(acc[r][1].u, xb, w[j].y);
                }
            }
        }
        #pragma unroll
        for (int r = 0; r < 4; ++r) {
            part[tid * 16 + r * 4 + 0] = acc[r][0].f.x;
            part[tid * 16 + r * 4 + 1] = acc[r][0].f.y;
            part[tid * 16 + r * 4 + 2] = acc[r][1].f.x;
            part[tid * 16 + r * 4 + 3] = acc[r][1].f.y;
        }
    }
    __syncthreads();

    // reduce + relu -> YT[f*36 + r]
    {
        const int r  = tid >> 3;
        const int fq = tid & 7;
        #pragma unroll
        for (int fl = 0; fl < 4; ++fl) {
            float v = 0.f;
            #pragma unroll
            for (int c = 0; c < 4; ++c)
                v += part[(c * 64 + (r >> 2) * 8 + fq) * 16 + (r & 3) * 4 + fl];
            YT[(fq * 4 + fl) * 36 + r] = fmaxf(v, 0.f);
        }
    }
    __syncthreads();

    // ---- GEMM2: warp owns 64-wide d chunk, lane owns 2 d; acc over row-pairs
    {
        const int lane = tid & 31;
        const int wq   = tid >> 5;
        const int d0   = wq * 64 + lane * 2;

        U2 acc[16][2];
        #pragma unroll
        for (int p = 0; p < 16; ++p) { acc[p][0].u = 0ull; acc[p][1].u = 0ull; }

        const float* w2p = f2 + slot * (FDIM * DDIM) + d0;
        #pragma unroll 4
        for (int k = 0; k < FDIM; ++k) {
            const float2 wv = __ldg((const float2*)(w2p + k * DDIM));
            const ull wb0 = bcast2(wv.x);
            const ull wb1 = bcast2(wv.y);
            const ulonglong2* yp = (const ulonglong2*)(YT + k * 36);
            #pragma unroll
            for (int q = 0; q < 8; ++q) {
                const ulonglong2 y = yp[q];     // rows (4q,4q+1),(4q+2,4q+3)
                ffma2(acc[2*q  ][0].u, y.x, wb0);
                ffma2(acc[2*q  ][1].u, y.x, wb1);
                ffma2(acc[2*q+1][0].u, y.y, wb0);
                ffma2(acc[2*q+1][1].u, y.y, wb1);
            }
        }
        #pragma unroll
        for (int p = 0; p < 16; ++p) {
            atomicAdd((float2*)(out + rowb[2*p    ] + d0),
                      make_float2(acc[p][0].f.x, acc[p][1].f.x));
            atomicAdd((float2*)(out + rowb[2*p + 1] + d0),
                      make_float2(acc[p][0].f.y, acc[p][1].f.y));
        }
    }
}

// ---------------------------------------------------------------------------
extern "C" void kernel_launch(void* const* d_in, const int* in_sizes, int n_in,
                              void* d_out, int out_size)
{
    (void)in_sizes; (void)n_in; (void)out_size;
    const float* x    = (const float*)d_in[0];
    const float* ctrl = (const float*)d_in[1];
    const float* f1   = (const float*)d_in[2];
    const float* f2   = (const float*)d_in[3];
    float* out = (float*)d_out;

    const int smem1 = 13312 * 4 + 2048;                            // 55296
    const int smem2 = (16384 + 4096 + 1152) * (int)sizeof(float);  // 86528
    cudaFuncSetAttribute(k_route,  cudaFuncAttributeMaxDynamicSharedMemorySize, smem1);
    cudaFuncSetAttribute(k_expert, cudaFuncAttributeMaxDynamicSharedMemorySize, smem2);

    k_route<<<NGROUPS, 256, smem1>>>(x, ctrl, out);
    k_expert<<<dim3(16, 64), 256, smem2>>>(x, f1, f2, out);
}